// round 7
// baseline (speedup 1.0000x reference)
#include <cuda_runtime.h>

// Problem dims
#define BB       4096
#define DIN      784
#define DZ       128
#define NTRIALS  256
#define BZ       (BB * DZ)
#define KSPLIT   7          // 49 K-tiles of 16 = 7 chunks x 7 tiles, exact

// Scratch (device globals => no allocations).
__device__ float g_part[KSPLIT][BZ];   // split-K partials for encoder

__device__ __forceinline__ float tanhf_fast(float x) {
    float y;
    asm("tanh.approx.f32 %0, %1;" : "=f"(y) : "f"(x));
    return y;
}

// ---------------------------------------------------------------------------
// Encoder split-K GEMM (R3 proven config): BM=128, BN=64, BK=16, 256 thr,
// 8x4 fragments, single-buffered. grid = (2, 32, 7). All dims exact.
// ---------------------------------------------------------------------------
__global__ __launch_bounds__(256)
void enc_gemm_splitk(const float* __restrict__ A,
                     const float* __restrict__ Bm)
{
    __shared__ float As[16][128];
    __shared__ float Bs[16][64];

    const int tid = threadIdx.x;
    const int tx  = tid & 15;
    const int ty  = tid >> 4;
    const int m0  = blockIdx.y * 128;
    const int n0  = blockIdx.x * 64;
    const int chunk = blockIdx.z;

    const int a_m = tid >> 1;
    const int a_k = (tid & 1) * 8;
    const int b_k = tid >> 4;
    const int b_n = (tid & 15) * 4;

    float acc[8][4];
    #pragma unroll
    for (int i = 0; i < 8; i++)
        #pragma unroll
        for (int j = 0; j < 4; j++) acc[i][j] = 0.f;

    #pragma unroll 1
    for (int t = chunk * 7; t < chunk * 7 + 7; t++) {
        const int k0 = t * 16;

        float4 av0 = *(const float4*)&A[(size_t)(m0 + a_m) * DIN + k0 + a_k];
        float4 av1 = *(const float4*)&A[(size_t)(m0 + a_m) * DIN + k0 + a_k + 4];
        As[a_k + 0][a_m] = av0.x; As[a_k + 1][a_m] = av0.y;
        As[a_k + 2][a_m] = av0.z; As[a_k + 3][a_m] = av0.w;
        As[a_k + 4][a_m] = av1.x; As[a_k + 5][a_m] = av1.y;
        As[a_k + 6][a_m] = av1.z; As[a_k + 7][a_m] = av1.w;

        *(float4*)&Bs[b_k][b_n] =
            *(const float4*)&Bm[(size_t)(k0 + b_k) * DZ + n0 + b_n];

        __syncthreads();

        #pragma unroll
        for (int k = 0; k < 16; k++) {
            float4 a0 = *(const float4*)&As[k][ty * 8];
            float4 a1 = *(const float4*)&As[k][ty * 8 + 4];
            float4 b4 = *(const float4*)&Bs[k][tx * 4];
            float ar[8] = {a0.x, a0.y, a0.z, a0.w, a1.x, a1.y, a1.z, a1.w};
            float br[4] = {b4.x, b4.y, b4.z, b4.w};
            #pragma unroll
            for (int i = 0; i < 8; i++)
                #pragma unroll
                for (int j = 0; j < 4; j++)
                    acc[i][j] = fmaf(ar[i], br[j], acc[i][j]);
        }
        __syncthreads();
    }

    float* dst = g_part[chunk];
    #pragma unroll
    for (int i = 0; i < 8; i++) {
        const int m = m0 + ty * 8 + i;
        float4 v = make_float4(acc[i][0], acc[i][1], acc[i][2], acc[i][3]);
        *(float4*)&dst[(size_t)m * DZ + n0 + tx * 4] = v;
    }
}

// ---------------------------------------------------------------------------
// Fused encoder-epilogue + exponential race, 2 elements per thread.
// Thread handles (b, z0) and (b, z0+1): float2 loads (half the LDGs),
// two independent chains (2x ILP). fp32 tanh.approx (f16x2 failed: per-output
// z error 1.8e-3 from fp16 quantization of h near the transition).
// Rate-aware geometric-tail exit: s * min(255, 6*rate) <= 2e-4 * zacc.
// ---------------------------------------------------------------------------
__global__ __launch_bounds__(256)
void race_kernel(const float* __restrict__ u,
                 const float* __restrict__ bias,
                 const float* __restrict__ prior,
                 float* __restrict__ out_du,
                 float* __restrict__ zout)
{
    const int gt = blockIdx.x * blockDim.x + threadIdx.x;  // element-pair id
    const int i0 = gt * 2;
    const int n0 = i0 & (DZ - 1);

    // encoder epilogue for both elements
    float a[2], exit_f[2];
    #pragma unroll
    for (int e = 0; e < 2; e++) {
        const int i = i0 + e;
        float v = g_part[0][i] + g_part[1][i] + g_part[2][i] + g_part[3][i]
                + g_part[4][i] + g_part[5][i] + g_part[6][i] + bias[n0 + e];
        float du = fminf(v, 5.0f);
        out_du[i] = du;
        float lr = fminf(du + fminf(prior[n0 + e], 5.0f), 5.0f);
        float rate = __expf(lr) + 1e-6f;
        a[e] = 0.34657359f / rate;                 // 0.5*ln2/rate
        exit_f[e] = fminf(255.0f, 6.0f * rate);
    }

    const float2* up = (const float2*)(u + i0);    // stride BZ/2 float2s

    float cum0 = 0.f, cum1 = 0.f, z0 = 0.f, z1 = 0.f;
    float2 buf[8];
    #pragma unroll
    for (int j = 0; j < 8; j++) buf[j] = up[(size_t)j * (BZ / 2)];

    #pragma unroll 1
    for (int t0 = 0; t0 < NTRIALS; t0 += 8) {
        float2 nbuf[8];
        if (t0 + 8 < NTRIALS) {
            #pragma unroll
            for (int j = 0; j < 8; j++)
                nbuf[j] = up[(size_t)(t0 + 8 + j) * (BZ / 2)];
        }

        float s0 = 0.f, s1 = 0.f;
        #pragma unroll
        for (int j = 0; j < 8; j++) {
            cum0 += __log2f(1.0f - buf[j].x);
            cum1 += __log2f(1.0f - buf[j].y);
            float h0 = fmaf(cum0, a[0], 0.5f);
            float h1 = fmaf(cum1, a[1], 0.5f);
            s0 = fmaf(0.5f, tanhf_fast(h0), 0.5f);
            s1 = fmaf(0.5f, tanhf_fast(h1), 0.5f);
            z0 += s0;
            z1 += s1;
        }

        bool done = (s0 * exit_f[0] <= z0 * 2e-4f + 1e-30f) &&
                    (s1 * exit_f[1] <= z1 * 2e-4f + 1e-30f);
        if (__all_sync(0xFFFFFFFFu, done)) break;

        #pragma unroll
        for (int j = 0; j < 8; j++) buf[j] = nbuf[j];
    }
    zout[i0]     = z0;
    zout[i0 + 1] = z1;
}

// ---------------------------------------------------------------------------
// Decoder GEMM (R3 proven config): y = sigmoid(z @ W_dec + b_dec)
// BM=128, BN=64, BK=16, 256 threads, 8x4 fragments, single-buffered.
// N=784 guarded. grid = (13, 32).
// ---------------------------------------------------------------------------
__global__ __launch_bounds__(256)
void dec_gemm(const float* __restrict__ A,
              const float* __restrict__ Bm,
              const float* __restrict__ bias,
              float* __restrict__ out)
{
    const int N = DIN, K = DZ;
    __shared__ float As[16][128];
    __shared__ float Bs[16][64];

    const int tid = threadIdx.x;
    const int tx  = tid & 15;
    const int ty  = tid >> 4;
    const int m0  = blockIdx.y * 128;
    const int n0  = blockIdx.x * 64;

    const int a_m = tid >> 1;
    const int a_k = (tid & 1) * 8;
    const int b_k = tid >> 4;
    const int b_n = (tid & 15) * 4;

    float acc[8][4];
    #pragma unroll
    for (int i = 0; i < 8; i++)
        #pragma unroll
        for (int j = 0; j < 4; j++) acc[i][j] = 0.f;

    #pragma unroll 1
    for (int k0 = 0; k0 < K; k0 += 16) {
        float4 av0 = *(const float4*)&A[(size_t)(m0 + a_m) * K + k0 + a_k];
        float4 av1 = *(const float4*)&A[(size_t)(m0 + a_m) * K + k0 + a_k + 4];
        As[a_k + 0][a_m] = av0.x; As[a_k + 1][a_m] = av0.y;
        As[a_k + 2][a_m] = av0.z; As[a_k + 3][a_m] = av0.w;
        As[a_k + 4][a_m] = av1.x; As[a_k + 5][a_m] = av1.y;
        As[a_k + 6][a_m] = av1.z; As[a_k + 7][a_m] = av1.w;

        const int gn = n0 + b_n;
        float4 bv;
        if (gn + 3 < N) {
            bv = *(const float4*)&Bm[(size_t)(k0 + b_k) * N + gn];
        } else {
            bv.x = (gn + 0 < N) ? Bm[(size_t)(k0 + b_k) * N + gn + 0] : 0.f;
            bv.y = (gn + 1 < N) ? Bm[(size_t)(k0 + b_k) * N + gn + 1] : 0.f;
            bv.z = (gn + 2 < N) ? Bm[(size_t)(k0 + b_k) * N + gn + 2] : 0.f;
            bv.w = (gn + 3 < N) ? Bm[(size_t)(k0 + b_k) * N + gn + 3] : 0.f;
        }
        *(float4*)&Bs[b_k][b_n] = bv;

        __syncthreads();

        #pragma unroll
        for (int k = 0; k < 16; k++) {
            float4 a0 = *(const float4*)&As[k][ty * 8];
            float4 a1 = *(const float4*)&As[k][ty * 8 + 4];
            float4 b4 = *(const float4*)&Bs[k][tx * 4];
            float ar[8] = {a0.x, a0.y, a0.z, a0.w, a1.x, a1.y, a1.z, a1.w};
            float br[4] = {b4.x, b4.y, b4.z, b4.w};
            #pragma unroll
            for (int i = 0; i < 8; i++)
                #pragma unroll
                for (int j = 0; j < 4; j++)
                    acc[i][j] = fmaf(ar[i], br[j], acc[i][j]);
        }
        __syncthreads();
    }

    #pragma unroll
    for (int i = 0; i < 8; i++) {
        const int m = m0 + ty * 8 + i;
        #pragma unroll
        for (int j = 0; j < 4; j++) {
            const int nn = n0 + tx * 4 + j;
            if (nn >= N) continue;
            float vv = acc[i][j] + bias[nn];
            float ex = __expf(-vv);
            out[(size_t)m * N + nn] = __fdividef(1.0f, 1.0f + ex);
        }
    }
}

// ---------------------------------------------------------------------------
// Launch. Input order: x, u, W_enc, b_enc, W_dec, b_dec, prior
// Output: du [BZ] | z [BZ] | y [B*DIN]
// ---------------------------------------------------------------------------
extern "C" void kernel_launch(void* const* d_in, const int* in_sizes, int n_in,
                              void* d_out, int out_size)
{
    const float* x     = (const float*)d_in[0];
    const float* u     = (const float*)d_in[1];
    const float* W_enc = (const float*)d_in[2];
    const float* b_enc = (const float*)d_in[3];
    const float* W_dec = (const float*)d_in[4];
    const float* b_dec = (const float*)d_in[5];
    const float* prior = (const float*)d_in[6];

    float* out_du = (float*)d_out;
    float* out_z  = out_du + (size_t)BZ;
    float* out_y  = out_z  + (size_t)BZ;

    // 1) encoder split-K GEMM
    {
        dim3 grid(DZ / 64, BB / 128, KSPLIT);
        enc_gemm_splitk<<<grid, 256>>>(x, W_enc);
    }
    // 2) fused epilogue + exponential race -> du, z  (2 elems/thread)
    race_kernel<<<BZ / 512, 256>>>(u, b_enc, prior, out_du, out_z);

    // 3) decoder GEMM: y = sigmoid(z @ W_dec + b_dec)
    {
        dim3 grid((DIN + 63) / 64, BB / 128);
        dec_gemm<<<grid, 256>>>(out_z, W_dec, b_dec, out_y);
    }
}

// round 8
// speedup vs baseline: 1.0987x; 1.0987x over previous
#include <cuda_runtime.h>

// Problem dims
#define BB       4096
#define DIN      784
#define DZ       128
#define NTRIALS  256
#define BZ       (BB * DZ)
#define KSPLIT   7          // 49 K-tiles of 16 = 7 chunks x 7 tiles, exact

// Scratch (device globals => no allocations).
__device__ float g_part[KSPLIT][BZ];   // split-K partials for encoder

__device__ __forceinline__ float tanhf_fast(float x) {
    float y;
    asm("tanh.approx.f32 %0, %1;" : "=f"(y) : "f"(x));
    return y;
}

// ---------------------------------------------------------------------------
// Encoder split-K GEMM (proven config): BM=128, BN=64, BK=16, 256 thr,
// 8x4 fragments, single-buffered. grid = (2, 32, 7). All dims exact.
// ---------------------------------------------------------------------------
__global__ __launch_bounds__(256)
void enc_gemm_splitk(const float* __restrict__ A,
                     const float* __restrict__ Bm)
{
    __shared__ float As[16][128];
    __shared__ float Bs[16][64];

    const int tid = threadIdx.x;
    const int tx  = tid & 15;
    const int ty  = tid >> 4;
    const int m0  = blockIdx.y * 128;
    const int n0  = blockIdx.x * 64;
    const int chunk = blockIdx.z;

    const int a_m = tid >> 1;
    const int a_k = (tid & 1) * 8;
    const int b_k = tid >> 4;
    const int b_n = (tid & 15) * 4;

    float acc[8][4];
    #pragma unroll
    for (int i = 0; i < 8; i++)
        #pragma unroll
        for (int j = 0; j < 4; j++) acc[i][j] = 0.f;

    #pragma unroll 1
    for (int t = chunk * 7; t < chunk * 7 + 7; t++) {
        const int k0 = t * 16;

        float4 av0 = *(const float4*)&A[(size_t)(m0 + a_m) * DIN + k0 + a_k];
        float4 av1 = *(const float4*)&A[(size_t)(m0 + a_m) * DIN + k0 + a_k + 4];
        As[a_k + 0][a_m] = av0.x; As[a_k + 1][a_m] = av0.y;
        As[a_k + 2][a_m] = av0.z; As[a_k + 3][a_m] = av0.w;
        As[a_k + 4][a_m] = av1.x; As[a_k + 5][a_m] = av1.y;
        As[a_k + 6][a_m] = av1.z; As[a_k + 7][a_m] = av1.w;

        *(float4*)&Bs[b_k][b_n] =
            *(const float4*)&Bm[(size_t)(k0 + b_k) * DZ + n0 + b_n];

        __syncthreads();

        #pragma unroll
        for (int k = 0; k < 16; k++) {
            float4 a0 = *(const float4*)&As[k][ty * 8];
            float4 a1 = *(const float4*)&As[k][ty * 8 + 4];
            float4 b4 = *(const float4*)&Bs[k][tx * 4];
            float ar[8] = {a0.x, a0.y, a0.z, a0.w, a1.x, a1.y, a1.z, a1.w};
            float br[4] = {b4.x, b4.y, b4.z, b4.w};
            #pragma unroll
            for (int i = 0; i < 8; i++)
                #pragma unroll
                for (int j = 0; j < 4; j++)
                    acc[i][j] = fmaf(ar[i], br[j], acc[i][j]);
        }
        __syncthreads();
    }

    float* dst = g_part[chunk];
    #pragma unroll
    for (int i = 0; i < 8; i++) {
        const int m = m0 + ty * 8 + i;
        float4 v = make_float4(acc[i][0], acc[i][1], acc[i][2], acc[i][3]);
        *(float4*)&dst[(size_t)m * DZ + n0 + tx * 4] = v;
    }
}

// ---------------------------------------------------------------------------
// Fused encoder-epilogue + exponential race. One thread per (b,z) — the
// minimum-span coalesced mapping (warp = 32 consecutive elements = one
// 128B line per trial); per-lane exit cannot save anything (line-granular
// loads, per-warp-instruction MUFU), so warp-uniform exit at 32-span is
// the structural optimum.
// Exit bound: expected geometric tail past exit is exactly ~s*rate
// (per-trial decay E[e^-dt] = r/(r+1)). Exit when s*2*rate <= 3e-4*zacc
// => expected tail <= 1.5e-4 relative (budget 1e-3 per output).
// ---------------------------------------------------------------------------
__global__ __launch_bounds__(256)
void race_kernel(const float* __restrict__ u,
                 const float* __restrict__ bias,
                 const float* __restrict__ prior,
                 float* __restrict__ out_du,
                 float* __restrict__ zout)
{
    const int i = blockIdx.x * blockDim.x + threadIdx.x;
    const int n = i & (DZ - 1);

    float v = g_part[0][i] + g_part[1][i] + g_part[2][i] + g_part[3][i]
            + g_part[4][i] + g_part[5][i] + g_part[6][i] + bias[n];
    float du = fminf(v, 5.0f);
    out_du[i] = du;
    float lr = fminf(du + fminf(prior[n], 5.0f), 5.0f);
    float rate = __expf(lr) + 1e-6f;
    const float a = 0.34657359f / rate;                // 0.5*ln2/rate
    const float exit_f = fminf(128.0f, 2.0f * rate);   // tail factor

    const float* up = u + i;

    float cum = 0.f, zacc = 0.f;
    float buf[8];
    #pragma unroll
    for (int j = 0; j < 8; j++) buf[j] = up[(size_t)j * BZ];

    #pragma unroll 1
    for (int t0 = 0; t0 < NTRIALS; t0 += 8) {
        float nbuf[8];
        if (t0 + 8 < NTRIALS) {
            #pragma unroll
            for (int j = 0; j < 8; j++)
                nbuf[j] = up[(size_t)(t0 + 8 + j) * BZ];
        }

        float s = 0.f;
        #pragma unroll
        for (int j = 0; j < 8; j++) {
            cum += __log2f(1.0f - buf[j]);          // negative, decreasing
            float h  = fmaf(cum, a, 0.5f);          // (1-times)/2
            s = fmaf(0.5f, tanhf_fast(h), 0.5f);    // sigmoid(1-times)
            zacc += s;
        }

        if (__all_sync(0xFFFFFFFFu, s * exit_f <= zacc * 3e-4f + 1e-30f))
            break;

        #pragma unroll
        for (int j = 0; j < 8; j++) buf[j] = nbuf[j];
    }
    zout[i] = zacc;
}

// ---------------------------------------------------------------------------
// Decoder GEMM (proven config): y = sigmoid(z @ W_dec + b_dec)
// BM=128, BN=64, BK=16, 256 threads, 8x4 fragments, single-buffered.
// N=784 guarded. grid = (13, 32).
// ---------------------------------------------------------------------------
__global__ __launch_bounds__(256)
void dec_gemm(const float* __restrict__ A,
              const float* __restrict__ Bm,
              const float* __restrict__ bias,
              float* __restrict__ out)
{
    const int N = DIN, K = DZ;
    __shared__ float As[16][128];
    __shared__ float Bs[16][64];

    const int tid = threadIdx.x;
    const int tx  = tid & 15;
    const int ty  = tid >> 4;
    const int m0  = blockIdx.y * 128;
    const int n0  = blockIdx.x * 64;

    const int a_m = tid >> 1;
    const int a_k = (tid & 1) * 8;
    const int b_k = tid >> 4;
    const int b_n = (tid & 15) * 4;

    float acc[8][4];
    #pragma unroll
    for (int i = 0; i < 8; i++)
        #pragma unroll
        for (int j = 0; j < 4; j++) acc[i][j] = 0.f;

    #pragma unroll 1
    for (int k0 = 0; k0 < K; k0 += 16) {
        float4 av0 = *(const float4*)&A[(size_t)(m0 + a_m) * K + k0 + a_k];
        float4 av1 = *(const float4*)&A[(size_t)(m0 + a_m) * K + k0 + a_k + 4];
        As[a_k + 0][a_m] = av0.x; As[a_k + 1][a_m] = av0.y;
        As[a_k + 2][a_m] = av0.z; As[a_k + 3][a_m] = av0.w;
        As[a_k + 4][a_m] = av1.x; As[a_k + 5][a_m] = av1.y;
        As[a_k + 6][a_m] = av1.z; As[a_k + 7][a_m] = av1.w;

        const int gn = n0 + b_n;
        float4 bv;
        if (gn + 3 < N) {
            bv = *(const float4*)&Bm[(size_t)(k0 + b_k) * N + gn];
        } else {
            bv.x = (gn + 0 < N) ? Bm[(size_t)(k0 + b_k) * N + gn + 0] : 0.f;
            bv.y = (gn + 1 < N) ? Bm[(size_t)(k0 + b_k) * N + gn + 1] : 0.f;
            bv.z = (gn + 2 < N) ? Bm[(size_t)(k0 + b_k) * N + gn + 2] : 0.f;
            bv.w = (gn + 3 < N) ? Bm[(size_t)(k0 + b_k) * N + gn + 3] : 0.f;
        }
        *(float4*)&Bs[b_k][b_n] = bv;

        __syncthreads();

        #pragma unroll
        for (int k = 0; k < 16; k++) {
            float4 a0 = *(const float4*)&As[k][ty * 8];
            float4 a1 = *(const float4*)&As[k][ty * 8 + 4];
            float4 b4 = *(const float4*)&Bs[k][tx * 4];
            float ar[8] = {a0.x, a0.y, a0.z, a0.w, a1.x, a1.y, a1.z, a1.w};
            float br[4] = {b4.x, b4.y, b4.z, b4.w};
            #pragma unroll
            for (int i = 0; i < 8; i++)
                #pragma unroll
                for (int j = 0; j < 4; j++)
                    acc[i][j] = fmaf(ar[i], br[j], acc[i][j]);
        }
        __syncthreads();
    }

    #pragma unroll
    for (int i = 0; i < 8; i++) {
        const int m = m0 + ty * 8 + i;
        #pragma unroll
        for (int j = 0; j < 4; j++) {
            const int nn = n0 + tx * 4 + j;
            if (nn >= N) continue;
            float vv = acc[i][j] + bias[nn];
            float ex = __expf(-vv);
            out[(size_t)m * N + nn] = __fdividef(1.0f, 1.0f + ex);
        }
    }
}

// ---------------------------------------------------------------------------
// Launch. Input order: x, u, W_enc, b_enc, W_dec, b_dec, prior
// Output: du [BZ] | z [BZ] | y [B*DIN]
// ---------------------------------------------------------------------------
extern "C" void kernel_launch(void* const* d_in, const int* in_sizes, int n_in,
                              void* d_out, int out_size)
{
    const float* x     = (const float*)d_in[0];
    const float* u     = (const float*)d_in[1];
    const float* W_enc = (const float*)d_in[2];
    const float* b_enc = (const float*)d_in[3];
    const float* W_dec = (const float*)d_in[4];
    const float* b_dec = (const float*)d_in[5];
    const float* prior = (const float*)d_in[6];

    float* out_du = (float*)d_out;
    float* out_z  = out_du + (size_t)BZ;
    float* out_y  = out_z  + (size_t)BZ;

    // 1) encoder split-K GEMM
    {
        dim3 grid(DZ / 64, BB / 128, KSPLIT);
        enc_gemm_splitk<<<grid, 256>>>(x, W_enc);
    }
    // 2) fused epilogue + exponential race -> du, z
    race_kernel<<<BZ / 256, 256>>>(u, b_enc, prior, out_du, out_z);

    // 3) decoder GEMM: y = sigmoid(z @ W_dec + b_dec)
    {
        dim3 grid((DIN + 63) / 64, BB / 128);
        dec_gemm<<<grid, 256>>>(out_z, W_dec, b_dec, out_y);
    }
}

// round 9
// speedup vs baseline: 1.4189x; 1.2914x over previous
#include <cuda_runtime.h>
#include <cstdint>

// Problem dims
#define BB       4096
#define DIN      784
#define DZ       128
#define NTRIALS  256
#define BZ       (BB * DZ)
#define KSPLIT   7          // 49 K-tiles of 16 = 7 chunks x 7 tiles, exact

// SMEM k-row strides (floats), padded so stride % 32 == 8 (conflict-free
// LDS.128 phases: bank offset 8*k + 4*g distinct within each phase of 8).
#define SA 136              // A tile: 16 k-rows x 128 m (permuted) + pad
#define SB 72               // B tile: 16 k-rows x 64 n (permuted) + pad

// Scratch (device globals => no allocations).
__device__ float g_part[KSPLIT][BZ];   // split-K partials for encoder

__device__ __forceinline__ float tanhf_fast(float x) {
    float y;
    asm("tanh.approx.f32 %0, %1;" : "=f"(y) : "f"(x));
    return y;
}

__device__ __forceinline__ uint32_t f2tf32(float x) {
    uint32_t r;
    asm("cvt.rna.tf32.f32 %0, %1;" : "=r"(r) : "f"(x));
    return r;
}

__device__ __forceinline__ void mma_tf32(float* c,
                                         uint32_t a0, uint32_t a1,
                                         uint32_t a2, uint32_t a3,
                                         uint32_t b0, uint32_t b1)
{
    asm volatile(
        "mma.sync.aligned.m16n8k8.row.col.f32.tf32.tf32.f32 "
        "{%0,%1,%2,%3}, {%4,%5,%6,%7}, {%8,%9}, {%0,%1,%2,%3};"
        : "+f"(c[0]), "+f"(c[1]), "+f"(c[2]), "+f"(c[3])
        : "r"(a0), "r"(a1), "r"(a2), "r"(a3), "r"(b0), "r"(b1));
}

// Permutation: row r in [0,32) of a warp group -> p = (r&7)*4 + (r>>3).
// Inverse: float4 at p4 = g*4 holds rows {g, g+8, g+16, g+24}.
__device__ __forceinline__ int permp(int r) { return (r & 7) * 4 + (r >> 3); }

// ---------------------------------------------------------------------------
// Warp-tile MMA consumer: 8 warps = 4(m) x 2(n); warp computes 32x32 of the
// 128x64 block tile. Per kstep (k8): 4 LDS.128 + 8 MMA.
// acc layout: acc[mt][nt][4], mt in {0,1} (16-row tiles), nt in {0..3}.
// ---------------------------------------------------------------------------
__device__ __forceinline__ void warp_mma_tile(const float* Asp, const float* Bsp,
                                              int wm, int wn, int lane,
                                              float acc[2][4][4])
{
    const int g  = lane >> 2;
    const int tg = lane & 3;
    #pragma unroll
    for (int kk = 0; kk < 16; kk += 8) {
        const int ka = kk + tg;
        uint4 a_lo = *(const uint4*)&Asp[ka * SA + wm * 32 + g * 4];
        uint4 a_hi = *(const uint4*)&Asp[(ka + 4) * SA + wm * 32 + g * 4];
        uint4 b_lo = *(const uint4*)&Bsp[ka * SB + wn * 32 + g * 4];
        uint4 b_hi = *(const uint4*)&Bsp[(ka + 4) * SB + wn * 32 + g * 4];

        uint32_t bl[4] = {b_lo.x, b_lo.y, b_lo.z, b_lo.w};
        uint32_t bh[4] = {b_hi.x, b_hi.y, b_hi.z, b_hi.w};

        #pragma unroll
        for (int nt = 0; nt < 4; nt++) {
            mma_tf32(acc[0][nt], a_lo.x, a_lo.y, a_hi.x, a_hi.y, bl[nt], bh[nt]);
            mma_tf32(acc[1][nt], a_lo.z, a_lo.w, a_hi.z, a_hi.w, bl[nt], bh[nt]);
        }
    }
}

// ---------------------------------------------------------------------------
// Encoder split-K GEMM (tf32 MMA): g_part[c] = x[:, chunk] @ W_enc[chunk, :]
// BM=128, BN=64, BK=16. grid = (2, 32, 7), 256 threads. All dims exact.
// ---------------------------------------------------------------------------
__global__ __launch_bounds__(256)
void enc_gemm_splitk(const float* __restrict__ A,
                     const float* __restrict__ Bm)
{
    __shared__ float Asp[16 * SA];
    __shared__ float Bsp[16 * SB];

    const int tid = threadIdx.x;
    const int m0  = blockIdx.y * 128;
    const int n0  = blockIdx.x * 64;
    const int chunk = blockIdx.z;

    const int wid  = tid >> 5, lane = tid & 31;
    const int wm   = wid >> 1, wn   = wid & 1;

    // A writer: row a_m, k = a_k..a_k+7
    const int a_m = tid >> 1;
    const int a_k = (tid & 1) * 8;
    const int pa  = (a_m >> 5) * 32 + permp(a_m & 31);
    // B writer: k row b_k, n = b_n..b_n+3
    const int b_k = tid >> 4;
    const int b_n = (tid & 15) * 4;

    float acc[2][4][4];
    #pragma unroll
    for (int i = 0; i < 2; i++)
        #pragma unroll
        for (int j = 0; j < 4; j++)
            #pragma unroll
            for (int q = 0; q < 4; q++) acc[i][j][q] = 0.f;

    #pragma unroll 1
    for (int t = chunk * 7; t < chunk * 7 + 7; t++) {
        const int k0 = t * 16;

        float4 av0 = *(const float4*)&A[(size_t)(m0 + a_m) * DIN + k0 + a_k];
        float4 av1 = *(const float4*)&A[(size_t)(m0 + a_m) * DIN + k0 + a_k + 4];
        float4 bv  = *(const float4*)&Bm[(size_t)(k0 + b_k) * DZ + n0 + b_n];

        float af[8] = {av0.x, av0.y, av0.z, av0.w, av1.x, av1.y, av1.z, av1.w};
        #pragma unroll
        for (int j = 0; j < 8; j++)
            Asp[(a_k + j) * SA + pa] = __uint_as_float(f2tf32(af[j]));

        float bf[4] = {bv.x, bv.y, bv.z, bv.w};
        #pragma unroll
        for (int j = 0; j < 4; j++) {
            const int c = b_n + j;
            Bsp[b_k * SB + (c >> 5) * 32 + permp(c & 31)] =
                __uint_as_float(f2tf32(bf[j]));
        }
        __syncthreads();

        warp_mma_tile(Asp, Bsp, wm, wn, lane, acc);
        __syncthreads();
    }

    // epilogue -> g_part[chunk]
    float* dst = g_part[chunk];
    const int g  = lane >> 2;
    const int tg = lane & 3;
    #pragma unroll
    for (int nt = 0; nt < 4; nt++) {
        const int n_el = n0 + wn * 32 + nt * 8 + tg * 2;
        #pragma unroll
        for (int mt = 0; mt < 2; mt++) {
            const int m_el = m0 + wm * 32 + mt * 16 + g;
            *(float2*)&dst[(size_t)m_el * DZ + n_el] =
                make_float2(acc[mt][nt][0], acc[mt][nt][1]);
            *(float2*)&dst[(size_t)(m_el + 8) * DZ + n_el] =
                make_float2(acc[mt][nt][2], acc[mt][nt][3]);
        }
    }
}

// ---------------------------------------------------------------------------
// Fused encoder-epilogue + exponential race (unchanged from 101.1us pass).
// One thread per (b,z); warp-uniform exit; expected geometric tail ~s*rate;
// exit when s*2*rate <= 3e-4*zacc => expected tail <= 1.5e-4 relative.
// ---------------------------------------------------------------------------
__global__ __launch_bounds__(256)
void race_kernel(const float* __restrict__ u,
                 const float* __restrict__ bias,
                 const float* __restrict__ prior,
                 float* __restrict__ out_du,
                 float* __restrict__ zout)
{
    const int i = blockIdx.x * blockDim.x + threadIdx.x;
    const int n = i & (DZ - 1);

    float v = g_part[0][i] + g_part[1][i] + g_part[2][i] + g_part[3][i]
            + g_part[4][i] + g_part[5][i] + g_part[6][i] + bias[n];
    float du = fminf(v, 5.0f);
    out_du[i] = du;
    float lr = fminf(du + fminf(prior[n], 5.0f), 5.0f);
    float rate = __expf(lr) + 1e-6f;
    const float a = 0.34657359f / rate;                // 0.5*ln2/rate
    const float exit_f = fminf(128.0f, 2.0f * rate);   // tail factor

    const float* up = u + i;

    float cum = 0.f, zacc = 0.f;
    float buf[8];
    #pragma unroll
    for (int j = 0; j < 8; j++) buf[j] = up[(size_t)j * BZ];

    #pragma unroll 1
    for (int t0 = 0; t0 < NTRIALS; t0 += 8) {
        float nbuf[8];
        if (t0 + 8 < NTRIALS) {
            #pragma unroll
            for (int j = 0; j < 8; j++)
                nbuf[j] = up[(size_t)(t0 + 8 + j) * BZ];
        }

        float s = 0.f;
        #pragma unroll
        for (int j = 0; j < 8; j++) {
            cum += __log2f(1.0f - buf[j]);          // negative, decreasing
            float h  = fmaf(cum, a, 0.5f);          // (1-times)/2
            s = fmaf(0.5f, tanhf_fast(h), 0.5f);    // sigmoid(1-times)
            zacc += s;
        }

        if (__all_sync(0xFFFFFFFFu, s * exit_f <= zacc * 3e-4f + 1e-30f))
            break;

        #pragma unroll
        for (int j = 0; j < 8; j++) buf[j] = nbuf[j];
    }
    zout[i] = zacc;
}

// ---------------------------------------------------------------------------
// Decoder GEMM (tf32 MMA): y = sigmoid(z @ W_dec + b_dec)
// BM=128, BN=64, BK=16, K=128 (8 tiles). N=784 guarded. grid = (13, 32).
// ---------------------------------------------------------------------------
__global__ __launch_bounds__(256)
void dec_gemm(const float* __restrict__ A,
              const float* __restrict__ Bm,
              const float* __restrict__ bias,
              float* __restrict__ out)
{
    const int N = DIN;
    __shared__ float Asp[16 * SA];
    __shared__ float Bsp[16 * SB];

    const int tid = threadIdx.x;
    const int m0  = blockIdx.y * 128;
    const int n0  = blockIdx.x * 64;

    const int wid  = tid >> 5, lane = tid & 31;
    const int wm   = wid >> 1, wn   = wid & 1;

    const int a_m = tid >> 1;
    const int a_k = (tid & 1) * 8;
    const int pa  = (a_m >> 5) * 32 + permp(a_m & 31);
    const int b_k = tid >> 4;
    const int b_n = (tid & 15) * 4;
    const int gn  = n0 + b_n;

    float acc[2][4][4];
    #pragma unroll
    for (int i = 0; i < 2; i++)
        #pragma unroll
        for (int j = 0; j < 4; j++)
            #pragma unroll
            for (int q = 0; q < 4; q++) acc[i][j][q] = 0.f;

    #pragma unroll 1
    for (int t = 0; t < 8; t++) {
        const int k0 = t * 16;

        float4 av0 = *(const float4*)&A[(size_t)(m0 + a_m) * DZ + k0 + a_k];
        float4 av1 = *(const float4*)&A[(size_t)(m0 + a_m) * DZ + k0 + a_k + 4];
        float4 bv  = make_float4(0.f, 0.f, 0.f, 0.f);
        if (gn + 3 < N)
            bv = *(const float4*)&Bm[(size_t)(k0 + b_k) * N + gn];

        float af[8] = {av0.x, av0.y, av0.z, av0.w, av1.x, av1.y, av1.z, av1.w};
        #pragma unroll
        for (int j = 0; j < 8; j++)
            Asp[(a_k + j) * SA + pa] = __uint_as_float(f2tf32(af[j]));

        float bf[4] = {bv.x, bv.y, bv.z, bv.w};
        #pragma unroll
        for (int j = 0; j < 4; j++) {
            const int c = b_n + j;
            Bsp[b_k * SB + (c >> 5) * 32 + permp(c & 31)] =
                __uint_as_float(f2tf32(bf[j]));
        }
        __syncthreads();

        warp_mma_tile(Asp, Bsp, wm, wn, lane, acc);
        __syncthreads();
    }

    // epilogue: sigmoid(acc + bias), guarded stores
    const int g  = lane >> 2;
    const int tg = lane & 3;
    #pragma unroll
    for (int nt = 0; nt < 4; nt++) {
        const int n_el = n0 + wn * 32 + nt * 8 + tg * 2;
        if (n_el >= N) continue;
        const float bi0 = bias[n_el], bi1 = bias[n_el + 1];
        #pragma unroll
        for (int mt = 0; mt < 2; mt++) {
            const int m_el = m0 + wm * 32 + mt * 16 + g;
            float v0 = acc[mt][nt][0] + bi0;
            float v1 = acc[mt][nt][1] + bi1;
            float v2 = acc[mt][nt][2] + bi0;
            float v3 = acc[mt][nt][3] + bi1;
            v0 = __fdividef(1.0f, 1.0f + __expf(-v0));
            v1 = __fdividef(1.0f, 1.0f + __expf(-v1));
            v2 = __fdividef(1.0f, 1.0f + __expf(-v2));
            v3 = __fdividef(1.0f, 1.0f + __expf(-v3));
            *(float2*)&out[(size_t)m_el * N + n_el]       = make_float2(v0, v1);
            *(float2*)&out[(size_t)(m_el + 8) * N + n_el] = make_float2(v2, v3);
        }
    }
}

// ---------------------------------------------------------------------------
// Launch. Input order: x, u, W_enc, b_enc, W_dec, b_dec, prior
// Output: du [BZ] | z [BZ] | y [B*DIN]
// ---------------------------------------------------------------------------
extern "C" void kernel_launch(void* const* d_in, const int* in_sizes, int n_in,
                              void* d_out, int out_size)
{
    const float* x     = (const float*)d_in[0];
    const float* u     = (const float*)d_in[1];
    const float* W_enc = (const float*)d_in[2];
    const float* b_enc = (const float*)d_in[3];
    const float* W_dec = (const float*)d_in[4];
    const float* b_dec = (const float*)d_in[5];
    const float* prior = (const float*)d_in[6];

    float* out_du = (float*)d_out;
    float* out_z  = out_du + (size_t)BZ;
    float* out_y  = out_z  + (size_t)BZ;

    // 1) encoder split-K GEMM (tf32 MMA)
    {
        dim3 grid(DZ / 64, BB / 128, KSPLIT);
        enc_gemm_splitk<<<grid, 256>>>(x, W_enc);
    }
    // 2) fused epilogue + exponential race -> du, z
    race_kernel<<<BZ / 256, 256>>>(u, b_enc, prior, out_du, out_z);

    // 3) decoder GEMM (tf32 MMA): y = sigmoid(z @ W_dec + b_dec)
    {
        dim3 grid((DIN + 63) / 64, BB / 128);
        dec_gemm<<<grid, 256>>>(out_z, W_dec, b_dec, out_y);
    }
}